// round 12
// baseline (speedup 1.0000x reference)
#include <cuda_runtime.h>
#include <cuda_fp16.h>
#include <math.h>
#include <stdint.h>

// Problem constants
#define BB    2
#define NN    8192
#define DD    256
#define HH    8
#define DHD   64
#define KNB   8
#define INNER 512
#define MTOT  (BB*NN)        // 16384
#define NQKV  (3*INNER)      // 1536 = Q | K | V

// 2-term fp16 split as extended-K plain GEMM
#define K2_QKV (2*DD)        // 512
#define K2_OUT (2*INNER)     // 1024

// KNN slicing
#define NSLICE 8
#define SLICE  (NN / NSLICE)   // 1024 candidates per slice
#define KCAP   16              // per-thread append buffer entries

// ---------------- static device scratch ----------------
__device__ __half g_X2 [(size_t)MTOT * K2_QKV];
__device__ __half g_WT [(size_t)NQKV * K2_QKV];
__device__ __half g_WTO[(size_t)DD * K2_OUT];
__device__ float  g_QKV[(size_t)MTOT * NQKV];
__device__ __half g_AT2[(size_t)MTOT * K2_OUT];
__device__ int    g_IDX[(size_t)MTOT * KNB];
__device__ float  g_PD [(size_t)MTOT * NSLICE * KNB];   // partial top-8 dists
__device__ int    g_PI [(size_t)MTOT * NSLICE * KNB];   // partial top-8 idxs

__device__ __forceinline__ uint32_t smem_u32(const void* p) {
    uint32_t a;
    asm("{ .reg .u64 t; cvta.to.shared.u64 t, %1; cvt.u32.u64 %0, t; }" : "=r"(a) : "l"(p));
    return a;
}
__device__ __forceinline__ void cp_async16(uint32_t s, const void* g) {
    asm volatile("cp.async.cg.shared.global [%0], [%1], 16;" :: "r"(s), "l"(g));
}
#define CP_COMMIT()  asm volatile("cp.async.commit_group;" ::: "memory")
#define CP_WAIT2()   asm volatile("cp.async.wait_group 2;" ::: "memory")

__device__ __forceinline__ void split_f16(float v, __half& h, __half& l) {
    h = __float2half(v);
    l = __float2half(v - __half2float(h));
}

// =============================================================================
// KNN scan: lane-per-query, branchless buffered selection.
// Round-12 inner loop:
//  - candidate pairs staged SoA: s_p1=(x0,x1,y0,y1), s_p2=(z0,z1,w0,w1)
//  - packed fma.rn.f32x2: 3 FFMA2 per 2 candidates (bit-exact vs scalar fmaf)
//  - 3-inst append: setp + @p st.shared.v2 + @p add addr (persistent abs addr)
// Lazy threshold (8th-best, updated at rare warp-collective flushes) only
// over-appends; flush drains in append(=index) order with strict-< ->
// exact jax.lax.top_k tie semantics.
// grid = (MTOT/256, NSLICE), block = 256. Dynamic smem 60KB.
// =============================================================================
#define KNN_SMEM (8192 + 8192 + 12288 + 256 * KCAP * 8)   // p1 + p2 + raw + buf

__global__ void __launch_bounds__(256) knn_scan_kernel(const float* __restrict__ pos)
{
    extern __shared__ char sm[];
    float4* s_p1  = (float4*)sm;                          // 8KB  (512 pairs)
    float4* s_p2  = (float4*)(sm + 8192);                 // 8KB
    float*  s_raw = (float*)(sm + 16384);                 // 12KB
    float2* s_buf = (float2*)(sm + 16384 + 12288);        // 32KB: [entry][tid]

    const int tid   = threadIdx.x;
    const int q     = blockIdx.x * 256 + tid;             // no batch straddle
    const int slice = blockIdx.y;
    const int b     = q >> 13;
    const int qn    = q & (NN - 1);
    const float* posb = pos + (size_t)b * NN * 3;

    const float qx2 = -2.0f * posb[qn * 3 + 0];
    const float qy2 = -2.0f * posb[qn * 3 + 1];
    const float qz2 = -2.0f * posb[qn * 3 + 2];
    // packed (v, v) constants for f32x2 math
    uint64_t qxp, qyp, qzp;
    asm("mov.b64 %0, {%1, %1};" : "=l"(qxp) : "f"(qx2));
    asm("mov.b64 %0, {%1, %1};" : "=l"(qyp) : "f"(qy2));
    asm("mov.b64 %0, {%1, %1};" : "=l"(qzp) : "f"(qz2));

    // stage this slice's 1024 positions (3072 floats = 768 float4)
    {
        const float4* src = (const float4*)(posb + (size_t)slice * SLICE * 3);
#pragma unroll
        for (int i = 0; i < 3; ++i)
            ((float4*)s_raw)[tid + 256 * i] = src[tid + 256 * i];
    }
    __syncthreads();
    // build pair-SoA: pair p = candidates (2p, 2p+1)
#pragma unroll
    for (int i = 0; i < 2; ++i) {
        const int p = tid + 256 * i;
        const float x0 = s_raw[p * 6 + 0], y0 = s_raw[p * 6 + 1], z0 = s_raw[p * 6 + 2];
        const float x1 = s_raw[p * 6 + 3], y1 = s_raw[p * 6 + 4], z1 = s_raw[p * 6 + 5];
        const float w0 = x0 * x0 + y0 * y0 + z0 * z0;
        const float w1 = x1 * x1 + y1 * y1 + z1 * z1;
        s_p1[p] = make_float4(x0, x1, y0, y1);
        s_p2[p] = make_float4(z0, z1, w0, w1);
    }
    __syncthreads();

    const float INF = __int_as_float(0x7f800000);
    float bd[8]; int bi[8];
#pragma unroll
    for (int j = 0; j < 8; ++j) { bd[j] = INF; bi[j] = 0x7fffffff; }
    float thr = INF;
    const int cbase = slice * SLICE;
    const uint32_t sbuf_tid = smem_u32(s_buf) + tid * 8;
    uint32_t addr = sbuf_tid;                             // next free entry (abs)

    // flush: drain buffers of ALL lanes together (rare, warp-uniform entry)
    auto flush = [&]() {
        int count = (int)((addr - sbuf_tid) >> 11);
        int mx = count;
#pragma unroll
        for (int o = 16; o; o >>= 1) mx = max(mx, __shfl_xor_sync(0xffffffffu, mx, o));
        for (int k = 0; k < mx; ++k) {
            const float2 e = s_buf[k * 256 + tid];
            if (k < count && e.x < bd[7]) {
                bd[7] = e.x; bi[7] = __float_as_int(e.y);
#pragma unroll
                for (int u = 7; u > 0; --u) {
                    if (bd[u] < bd[u - 1]) {              // strict: stable on ties
                        float tf = bd[u - 1]; bd[u - 1] = bd[u]; bd[u] = tf;
                        int   ti = bi[u - 1]; bi[u - 1] = bi[u]; bi[u] = ti;
                    }
                }
            }
        }
        thr = bd[7];
        addr = sbuf_tid;
    };

    for (int c0 = 0; c0 < SLICE; c0 += 8) {
        // 4 packed-pair distance computations (bit-exact vs scalar fmaf chain)
        float t[8];
#pragma unroll
        for (int pp = 0; pp < 4; ++pp) {
            const float4 a  = s_p1[(c0 >> 1) + pp];       // x0,x1,y0,y1
            const float4 b2 = s_p2[(c0 >> 1) + pp];       // z0,z1,w0,w1
            asm("{\n\t"
                ".reg .b64 X, Y, Z, W, T;\n\t"
                "mov.b64 X, {%2, %3};\n\t"
                "mov.b64 Y, {%4, %5};\n\t"
                "mov.b64 Z, {%6, %7};\n\t"
                "mov.b64 W, {%8, %9};\n\t"
                "fma.rn.f32x2 T, Z, %10, W;\n\t"
                "fma.rn.f32x2 T, Y, %11, T;\n\t"
                "fma.rn.f32x2 T, X, %12, T;\n\t"
                "mov.b64 {%0, %1}, T;\n\t"
                "}"
                : "=f"(t[2 * pp]), "=f"(t[2 * pp + 1])
                : "f"(a.x), "f"(a.y), "f"(a.z), "f"(a.w),
                  "f"(b2.x), "f"(b2.y), "f"(b2.z), "f"(b2.w),
                  "l"(qzp), "l"(qyp), "l"(qxp));
        }
        // compact appends: setp + @p store + @p bump (3 inst each)
#pragma unroll
        for (int u = 0; u < 8; ++u) {
            asm volatile(
                "{\n\t.reg .pred p;\n\t"
                "setp.lt.f32 p, %1, %2;\n\t"
                "@p st.shared.v2.f32 [%0], {%1, %3};\n\t"
                "@p add.u32 %0, %0, 2048;\n\t}"
                : "+r"(addr)
                : "f"(t[u]), "f"(thr),
                  "f"(__int_as_float(cbase + c0 + u))
                : "memory");
        }
        if (__ballot_sync(0xffffffffu,
                          addr - sbuf_tid >= (KCAP - 8) * 2048))   // warp-uniform
            flush();
    }
    flush();

    float* pd = g_PD + ((size_t)q * NSLICE + slice) * 8;
    int*   pi = g_PI + ((size_t)q * NSLICE + slice) * 8;
#pragma unroll
    for (int j = 0; j < 8; ++j) { pd[j] = bd[j]; pi[j] = bi[j]; }
}

// =============================================================================
// KNN merge: per query, 8-way merge of sorted 8-lists with (dist, idx)
// tie-break (lower index wins) — exact jax.lax.top_k order.
// =============================================================================
__global__ void __launch_bounds__(256) knn_merge_kernel()
{
    const int q = blockIdx.x * 256 + threadIdx.x;
    const float* pd = g_PD + (size_t)q * (NSLICE * 8);
    const int*   pi = g_PI + (size_t)q * (NSLICE * 8);
    const float INF = __int_as_float(0x7f800000);

    float hd[NSLICE]; int hi_[NSLICE]; int pp[NSLICE];
#pragma unroll
    for (int s = 0; s < NSLICE; ++s) {
        hd[s] = pd[s * 8]; hi_[s] = pi[s * 8]; pp[s] = 0;
    }

    int out[8];
#pragma unroll
    for (int r = 0; r < 8; ++r) {
        float bdv = hd[0]; int biv = hi_[0]; int sel = 0;
#pragma unroll
        for (int s = 1; s < NSLICE; ++s)
            if (hd[s] < bdv || (hd[s] == bdv && hi_[s] < biv)) {
                bdv = hd[s]; biv = hi_[s]; sel = s;
            }
        out[r] = biv;
#pragma unroll
        for (int s = 0; s < NSLICE; ++s)
            if (sel == s) {
                ++pp[s];
                const bool ok = pp[s] < 8;
                hd[s]  = ok ? pd[s * 8 + pp[s]] : INF;
                hi_[s] = ok ? pi[s * 8 + pp[s]] : 0x7fffffff;
            }
    }
    *(int4*)&g_IDX[(size_t)q * 8]     = make_int4(out[0], out[1], out[2], out[3]);
    *(int4*)&g_IDX[(size_t)q * 8 + 4] = make_int4(out[4], out[5], out[6], out[7]);
}

// =============================================================================
// Conversions: fp32 -> fp16 (A: hi|lo split, B: hi duplicated), extended-K.
// =============================================================================
__global__ void __launch_bounds__(256) conv_x_kernel(const float* __restrict__ x)
{
    const int idx = blockIdx.x * 256 + threadIdx.x;
    const int row = idx >> 8, k = idx & 255;
    __half h, l;
    split_f16(x[idx], h, l);
    __half* r = g_X2 + (size_t)row * K2_QKV;
    r[k] = h; r[DD + k] = l;
}

__global__ void __launch_bounds__(256) conv_wqkv_kernel(const float* __restrict__ Wq,
                                                        const float* __restrict__ Wkv)
{
    const int idx = blockIdx.x * 256 + threadIdx.x;
    const int n = idx >> 8, k = idx & 255;
    const float v = (n < INNER) ? Wq[(size_t)k * INNER + n]
                                : Wkv[(size_t)k * (2 * INNER) + (n - INNER)];
    const __half h = __float2half(v);
    __half* r = g_WT + (size_t)n * K2_QKV;
    r[k] = h; r[DD + k] = h;
}

__global__ void __launch_bounds__(256) conv_wout_kernel(const float* __restrict__ Wout)
{
    const int idx = blockIdx.x * 256 + threadIdx.x;
    const int n = idx >> 9, k = idx & 511;
    const __half h = __float2half(Wout[(size_t)k * DD + n]);
    __half* r = g_WTO + (size_t)n * K2_OUT;
    r[k] = h; r[INNER + k] = h;
}

// =============================================================================
// fp16 tensor-core GEMM via mma.sync (unchanged — 82.5us @ tensor 51% on QKV).
// =============================================================================
#define GSTAGES   3
#define GSTAGE_B  32768
#define GEMM_SMEM (GSTAGES * GSTAGE_B)        // 96 KB

__device__ __forceinline__ void mma_f16(float* d, const uint32_t* a, const uint32_t* b)
{
    asm volatile(
        "mma.sync.aligned.m16n8k16.row.col.f32.f16.f16.f32 "
        "{%0,%1,%2,%3}, {%4,%5,%6,%7}, {%8,%9}, {%0,%1,%2,%3};"
        : "+f"(d[0]), "+f"(d[1]), "+f"(d[2]), "+f"(d[3])
        : "r"(a[0]), "r"(a[1]), "r"(a[2]), "r"(a[3]), "r"(b[0]), "r"(b[1]));
}

__device__ __forceinline__ void ldsm_x4(uint32_t* r, uint32_t a)
{
    asm volatile("ldmatrix.sync.aligned.m8n8.x4.shared.b16 {%0,%1,%2,%3}, [%4];"
        : "=r"(r[0]), "=r"(r[1]), "=r"(r[2]), "=r"(r[3]) : "r"(a));
}

__global__ void __launch_bounds__(256, 2) gemm_mma_kernel(
    const __half* __restrict__ A,
    const __half* __restrict__ Bt,
    float* __restrict__ C, const float* __restrict__ bias,
    int Nglob, int K2)
{
    extern __shared__ char smem[];
    const uint32_t sb = smem_u32(smem);
    const int tid  = threadIdx.x;
    const int warp = tid >> 5, lane = tid & 31;
    const int wm = warp & 1, wn = warp >> 1;
    const int m0 = blockIdx.y * 128, n0 = blockIdx.x * 128;
    const int nch = K2 >> 6;

    float acc[4][4][4];
#pragma unroll
    for (int i = 0; i < 4; ++i)
#pragma unroll
        for (int j = 0; j < 4; ++j)
#pragma unroll
            for (int t = 0; t < 4; ++t) acc[i][j][t] = 0.0f;

    const int a_row = wm * 64 + (lane & 15);
    const int a_k   = (lane >> 4);
    const int b_row = wn * 32 + ((lane & 16) >> 1) + (lane & 7);
    const int b_k   = ((lane >> 3) & 1);

    auto load_stage = [&](int s, int kc) {
        const uint32_t st = sb + s * GSTAGE_B;
#pragma unroll
        for (int it = 0; it < 4; ++it) {
            const int idx = it * 256 + tid;
            const int row = idx >> 3, c = idx & 7;
            cp_async16(st + row * 128 + ((c ^ (row & 7)) << 4),
                       A + (size_t)(m0 + row) * K2 + kc * 64 + c * 8);
        }
#pragma unroll
        for (int it = 0; it < 4; ++it) {
            const int idx = it * 256 + tid;
            const int row = idx >> 3, c = idx & 7;
            cp_async16(st + 16384 + row * 128 + ((c ^ (row & 7)) << 4),
                       Bt + (size_t)(n0 + row) * K2 + kc * 64 + c * 8);
        }
    };

    load_stage(0, 0); CP_COMMIT();
    load_stage(1, 1); CP_COMMIT();

    for (int i = 0; i < nch; ++i) {
        if (i + 2 < nch) load_stage((i + 2) % GSTAGES, i + 2);
        CP_COMMIT();
        CP_WAIT2();
        __syncthreads();

        const uint32_t stA = sb + (i % GSTAGES) * GSTAGE_B;
        const uint32_t stB = stA + 16384;

#pragma unroll
        for (int ks = 0; ks < 4; ++ks) {
            uint32_t af[4][4], bf[2][4];
#pragma unroll
            for (int mi = 0; mi < 4; ++mi) {
                const int row = a_row + mi * 16;
                const int kc  = 2 * ks + a_k;
                ldsm_x4(af[mi], stA + row * 128 + ((kc ^ (row & 7)) << 4));
            }
#pragma unroll
            for (int h = 0; h < 2; ++h) {
                const int row = b_row + h * 16;
                const int kc  = 2 * ks + b_k;
                ldsm_x4(bf[h], stB + row * 128 + ((kc ^ (row & 7)) << 4));
            }
#pragma unroll
            for (int mi = 0; mi < 4; ++mi)
#pragma unroll
                for (int nj = 0; nj < 4; ++nj)
                    mma_f16(acc[mi][nj], af[mi], &bf[nj >> 1][(nj & 1) * 2]);
        }
        __syncthreads();
    }

    const int g = lane >> 2, tg = lane & 3;
#pragma unroll
    for (int mi = 0; mi < 4; ++mi) {
        const int r0 = m0 + wm * 64 + mi * 16 + g;
#pragma unroll
        for (int nj = 0; nj < 4; ++nj) {
            const int col = n0 + wn * 32 + nj * 8 + tg * 2;
            float b0 = 0.0f, b1 = 0.0f;
            if (bias) { b0 = bias[col]; b1 = bias[col + 1]; }
            float2 o0 = make_float2(acc[mi][nj][0] + b0, acc[mi][nj][1] + b1);
            float2 o1 = make_float2(acc[mi][nj][2] + b0, acc[mi][nj][3] + b1);
            *(float2*)&C[(size_t)r0 * Nglob + col]       = o0;
            *(float2*)&C[(size_t)(r0 + 8) * Nglob + col] = o1;
        }
    }
}

// =============================================================================
// Attention (unchanged): one block per point, 8 warps = 8 heads.
// =============================================================================
__global__ void __launch_bounds__(256) attn_kernel()
{
    const int point = blockIdx.x;
    const int warp  = threadIdx.x >> 5;
    const int lane  = threadIdx.x & 31;
    const int b     = point >> 13;
    const int baseb = b * NN;

    const int* idxp = g_IDX + (size_t)point * 8;
    const float2 qh = *(const float2*)&g_QKV[(size_t)point * NQKV + warp * DHD + lane * 2];

    float dots[8];
    int   nbs[8];
#pragma unroll
    for (int k = 0; k < 8; ++k) {
        const int nb = idxp[k];
        nbs[k] = nb;
        const float2 kk = *(const float2*)&g_QKV[(size_t)(baseb + nb) * NQKV + INNER + warp * DHD + lane * 2];
        float d = qh.x * kk.x + qh.y * kk.y;
#pragma unroll
        for (int o = 16; o; o >>= 1) d += __shfl_xor_sync(0xffffffffu, d, o);
        dots[k] = d * 0.125f;
    }

    float m = dots[0];
#pragma unroll
    for (int k = 1; k < 8; ++k) m = fmaxf(m, dots[k]);
    float e[8], s = 0.0f;
#pragma unroll
    for (int k = 0; k < 8; ++k) { e[k] = expf(dots[k] - m); s += e[k]; }
    const float inv = 1.0f / s;

    float2 acc = make_float2(0.0f, 0.0f);
#pragma unroll
    for (int k = 0; k < 8; ++k) {
        const float2 vv = *(const float2*)&g_QKV[(size_t)(baseb + nbs[k]) * NQKV + 2 * INNER + warp * DHD + lane * 2];
        const float a = e[k] * inv;
        acc.x = fmaf(a, vv.x, acc.x);
        acc.y = fmaf(a, vv.y, acc.y);
    }

    __half hx, lx, hy, ly;
    split_f16(acc.x, hx, lx);
    split_f16(acc.y, hy, ly);
    __half2 hp; hp.x = hx; hp.y = hy;
    __half2 lp; lp.x = lx; lp.y = ly;
    __half* r = g_AT2 + (size_t)point * K2_OUT + warp * DHD + lane * 2;
    *(__half2*)(r)         = hp;
    *(__half2*)(r + INNER) = lp;
}

// =============================================================================
extern "C" void kernel_launch(void* const* d_in, const int* in_sizes, int n_in,
                              void* d_out, int out_size)
{
    const float* x    = (const float*)d_in[0];
    const float* pos  = (const float*)d_in[1];
    const float* Wq   = (const float*)d_in[2];
    const float* Wkv  = (const float*)d_in[3];
    const float* Wout = (const float*)d_in[4];
    const float* bout = (const float*)d_in[5];
    float* out = (float*)d_out;

    cudaFuncSetAttribute(gemm_mma_kernel,
                         cudaFuncAttributeMaxDynamicSharedMemorySize, GEMM_SMEM);
    cudaFuncSetAttribute(knn_scan_kernel,
                         cudaFuncAttributeMaxDynamicSharedMemorySize, KNN_SMEM);

    __half *pX2, *pWT, *pWTO, *pAT2;
    float *pQKV;
    cudaGetSymbolAddress((void**)&pX2,  g_X2);
    cudaGetSymbolAddress((void**)&pWT,  g_WT);
    cudaGetSymbolAddress((void**)&pWTO, g_WTO);
    cudaGetSymbolAddress((void**)&pQKV, g_QKV);
    cudaGetSymbolAddress((void**)&pAT2, g_AT2);

    // knn_scan at the deterministically-profiled 4th launch slot.
    conv_x_kernel<<<MTOT * DD / 256, 256>>>(x);
    conv_wqkv_kernel<<<NQKV * DD / 256, 256>>>(Wq, Wkv);
    conv_wout_kernel<<<DD * INNER / 256, 256>>>(Wout);

    // 4) KNN scan (f32x2 packed distances + 3-inst appends) — profiled
    knn_scan_kernel<<<dim3(MTOT / 256, NSLICE), 256, KNN_SMEM>>>(pos);

    // 5) KNN merge (8-way sorted merge, tie-break on index)
    knn_merge_kernel<<<MTOT / 256, 256>>>();

    // 6) fused QKV = x @ [Wq|Wkv]
    gemm_mma_kernel<<<dim3(NQKV / 128, MTOT / 128), 256, GEMM_SMEM>>>(
        pX2, pWT, pQKV, nullptr, NQKV, K2_QKV);

    // 7) neighbor attention
    attn_kernel<<<MTOT, 256>>>();

    // 8) out = ATT @ Wout + bout
    gemm_mma_kernel<<<dim3(DD / 128, MTOT / 128), 256, GEMM_SMEM>>>(
        pAT2, pWTO, out, bout, DD, K2_OUT);
}

// round 13
// speedup vs baseline: 1.0116x; 1.0116x over previous
#include <cuda_runtime.h>
#include <cuda_fp16.h>
#include <math.h>
#include <stdint.h>

// Problem constants
#define BB    2
#define NN    8192
#define DD    256
#define HH    8
#define DHD   64
#define KNB   8
#define INNER 512
#define MTOT  (BB*NN)        // 16384
#define NQKV  (3*INNER)      // 1536 = Q | K | V

// 2-term fp16 split as extended-K plain GEMM
#define K2_QKV (2*DD)        // 512
#define K2_OUT (2*INNER)     // 1024

// KNN slicing
#define NSLICE 8
#define SLICE  (NN / NSLICE)   // 1024 candidates per slice
#define KCAP   16              // per-thread append buffer entries

#define SCAN_BLOCKS (MTOT / 256 * NSLICE)    // 512
#define QKV_BLOCKS  (NQKV / 128 * MTOT / 128) // 1536
#define FUSED_GRID  (SCAN_BLOCKS + QKV_BLOCKS) // 2048 (scan = every 4th bid)

// ---------------- static device scratch ----------------
__device__ __half g_X2 [(size_t)MTOT * K2_QKV];
__device__ __half g_WT [(size_t)NQKV * K2_QKV];
__device__ __half g_WTO[(size_t)DD * K2_OUT];
__device__ float  g_QKV[(size_t)MTOT * NQKV];
__device__ __half g_AT2[(size_t)MTOT * K2_OUT];
__device__ int    g_IDX[(size_t)MTOT * KNB];
__device__ float  g_PD [(size_t)MTOT * NSLICE * KNB];   // partial top-8 dists
__device__ int    g_PI [(size_t)MTOT * NSLICE * KNB];   // partial top-8 idxs

__device__ __forceinline__ uint32_t smem_u32(const void* p) {
    uint32_t a;
    asm("{ .reg .u64 t; cvta.to.shared.u64 t, %1; cvt.u32.u64 %0, t; }" : "=r"(a) : "l"(p));
    return a;
}
__device__ __forceinline__ void cp_async16(uint32_t s, const void* g) {
    asm volatile("cp.async.cg.shared.global [%0], [%1], 16;" :: "r"(s), "l"(g));
}
#define CP_COMMIT()  asm volatile("cp.async.commit_group;" ::: "memory")
#define CP_WAIT2()   asm volatile("cp.async.wait_group 2;" ::: "memory")

__device__ __forceinline__ void split_f16(float v, __half& h, __half& l) {
    h = __float2half(v);
    l = __float2half(v - __half2float(h));
}

// =============================================================================
// KNN scan BODY: lane-per-query, branchless buffered selection (R11 scalar
// distances + R12 3-inst persistent-address append). Lazy threshold only
// over-appends; flush drains in append(=index) order with strict-< ->
// exact jax.lax.top_k tie semantics. Uses first 60KB of dynamic smem.
// =============================================================================
__device__ __forceinline__ void knn_scan_body(int sbx, int slice,
                                              const float* __restrict__ pos,
                                              char* sm)
{
    float4* s_c4  = (float4*)sm;                          // 16KB
    float*  s_raw = (float*)(sm + 16384);                 // 12KB
    float2* s_buf = (float2*)(sm + 16384 + 12288);        // 32KB: [entry][tid]

    const int tid = threadIdx.x;
    const int q   = sbx * 256 + tid;                      // no batch straddle
    const int b   = q >> 13;
    const int qn  = q & (NN - 1);
    const float* posb = pos + (size_t)b * NN * 3;

    const float qx2 = -2.0f * posb[qn * 3 + 0];
    const float qy2 = -2.0f * posb[qn * 3 + 1];
    const float qz2 = -2.0f * posb[qn * 3 + 2];

    // stage this slice's 1024 positions (3072 floats = 768 float4)
    {
        const float4* src = (const float4*)(posb + (size_t)slice * SLICE * 3);
#pragma unroll
        for (int i = 0; i < 3; ++i)
            ((float4*)s_raw)[tid + 256 * i] = src[tid + 256 * i];
    }
    __syncthreads();
#pragma unroll
    for (int i = 0; i < 4; ++i) {
        const int c = tid + 256 * i;
        const float cx = s_raw[c * 3 + 0];
        const float cy = s_raw[c * 3 + 1];
        const float cz = s_raw[c * 3 + 2];
        s_c4[c] = make_float4(cx, cy, cz, cx * cx + cy * cy + cz * cz);
    }
    __syncthreads();

    const float INF = __int_as_float(0x7f800000);
    float bd[8]; int bi[8];
#pragma unroll
    for (int j = 0; j < 8; ++j) { bd[j] = INF; bi[j] = 0x7fffffff; }
    float thr = INF;
    const int cbase = slice * SLICE;
    const uint32_t sbuf_tid = smem_u32(s_buf) + tid * 8;
    uint32_t addr = sbuf_tid;

    auto flush = [&]() {
        int count = (int)((addr - sbuf_tid) >> 11);
        int mx = count;
#pragma unroll
        for (int o = 16; o; o >>= 1) mx = max(mx, __shfl_xor_sync(0xffffffffu, mx, o));
        for (int k = 0; k < mx; ++k) {
            const float2 e = s_buf[k * 256 + tid];
            if (k < count && e.x < bd[7]) {
                bd[7] = e.x; bi[7] = __float_as_int(e.y);
#pragma unroll
                for (int u = 7; u > 0; --u) {
                    if (bd[u] < bd[u - 1]) {              // strict: stable on ties
                        float tf = bd[u - 1]; bd[u - 1] = bd[u]; bd[u] = tf;
                        int   ti = bi[u - 1]; bi[u - 1] = bi[u]; bi[u] = ti;
                    }
                }
            }
        }
        thr = bd[7];
        addr = sbuf_tid;
    };

    for (int c0 = 0; c0 < SLICE; c0 += 8) {
        float t[8];
#pragma unroll
        for (int u = 0; u < 8; ++u) {
            const float4 p = s_c4[c0 + u];                // broadcast LDS
            t[u] = fmaf(p.x, qx2, fmaf(p.y, qy2, fmaf(p.z, qz2, p.w)));
        }
#pragma unroll
        for (int u = 0; u < 8; ++u) {
            asm volatile(
                "{\n\t.reg .pred p;\n\t"
                "setp.lt.f32 p, %1, %2;\n\t"
                "@p st.shared.v2.f32 [%0], {%1, %3};\n\t"
                "@p add.u32 %0, %0, 2048;\n\t}"
                : "+r"(addr)
                : "f"(t[u]), "f"(thr),
                  "f"(__int_as_float(cbase + c0 + u))
                : "memory");
        }
        if (__ballot_sync(0xffffffffu,
                          addr - sbuf_tid >= (KCAP - 8) * 2048))
            flush();
    }
    flush();

    float* pd = g_PD + ((size_t)q * NSLICE + slice) * 8;
    int*   pi = g_PI + ((size_t)q * NSLICE + slice) * 8;
#pragma unroll
    for (int j = 0; j < 8; ++j) { pd[j] = bd[j]; pi[j] = bi[j]; }
}

// =============================================================================
// fp16 tensor-core GEMM BODY via mma.sync (logic identical to round 7-12):
// CTA 128x128, 8 warps (2x4) of m64 x n32, K-chunk 64, 3-stage cp.async,
// PLAIN ldmatrix for N-major B.
// =============================================================================
#define GSTAGES   3
#define GSTAGE_B  32768
#define GEMM_SMEM (GSTAGES * GSTAGE_B)        // 96 KB

__device__ __forceinline__ void mma_f16(float* d, const uint32_t* a, const uint32_t* b)
{
    asm volatile(
        "mma.sync.aligned.m16n8k16.row.col.f32.f16.f16.f32 "
        "{%0,%1,%2,%3}, {%4,%5,%6,%7}, {%8,%9}, {%0,%1,%2,%3};"
        : "+f"(d[0]), "+f"(d[1]), "+f"(d[2]), "+f"(d[3])
        : "r"(a[0]), "r"(a[1]), "r"(a[2]), "r"(a[3]), "r"(b[0]), "r"(b[1]));
}

__device__ __forceinline__ void ldsm_x4(uint32_t* r, uint32_t a)
{
    asm volatile("ldmatrix.sync.aligned.m8n8.x4.shared.b16 {%0,%1,%2,%3}, [%4];"
        : "=r"(r[0]), "=r"(r[1]), "=r"(r[2]), "=r"(r[3]) : "r"(a));
}

__device__ __forceinline__ void gemm_body(
    int bx, int by, char* smem,
    const __half* __restrict__ A,
    const __half* __restrict__ Bt,
    float* __restrict__ C, const float* __restrict__ bias,
    int Nglob, int K2)
{
    const uint32_t sb = smem_u32(smem);
    const int tid  = threadIdx.x;
    const int warp = tid >> 5, lane = tid & 31;
    const int wm = warp & 1, wn = warp >> 1;
    const int m0 = by * 128, n0 = bx * 128;
    const int nch = K2 >> 6;

    float acc[4][4][4];
#pragma unroll
    for (int i = 0; i < 4; ++i)
#pragma unroll
        for (int j = 0; j < 4; ++j)
#pragma unroll
            for (int t = 0; t < 4; ++t) acc[i][j][t] = 0.0f;

    const int a_row = wm * 64 + (lane & 15);
    const int a_k   = (lane >> 4);
    const int b_row = wn * 32 + ((lane & 16) >> 1) + (lane & 7);
    const int b_k   = ((lane >> 3) & 1);

    auto load_stage = [&](int s, int kc) {
        const uint32_t st = sb + s * GSTAGE_B;
#pragma unroll
        for (int it = 0; it < 4; ++it) {
            const int idx = it * 256 + tid;
            const int row = idx >> 3, c = idx & 7;
            cp_async16(st + row * 128 + ((c ^ (row & 7)) << 4),
                       A + (size_t)(m0 + row) * K2 + kc * 64 + c * 8);
        }
#pragma unroll
        for (int it = 0; it < 4; ++it) {
            const int idx = it * 256 + tid;
            const int row = idx >> 3, c = idx & 7;
            cp_async16(st + 16384 + row * 128 + ((c ^ (row & 7)) << 4),
                       Bt + (size_t)(n0 + row) * K2 + kc * 64 + c * 8);
        }
    };

    load_stage(0, 0); CP_COMMIT();
    load_stage(1, 1); CP_COMMIT();

    for (int i = 0; i < nch; ++i) {
        if (i + 2 < nch) load_stage((i + 2) % GSTAGES, i + 2);
        CP_COMMIT();
        CP_WAIT2();
        __syncthreads();

        const uint32_t stA = sb + (i % GSTAGES) * GSTAGE_B;
        const uint32_t stB = stA + 16384;

#pragma unroll
        for (int ks = 0; ks < 4; ++ks) {
            uint32_t af[4][4], bf[2][4];
#pragma unroll
            for (int mi = 0; mi < 4; ++mi) {
                const int row = a_row + mi * 16;
                const int kc  = 2 * ks + a_k;
                ldsm_x4(af[mi], stA + row * 128 + ((kc ^ (row & 7)) << 4));
            }
#pragma unroll
            for (int h = 0; h < 2; ++h) {
                const int row = b_row + h * 16;
                const int kc  = 2 * ks + b_k;
                ldsm_x4(bf[h], stB + row * 128 + ((kc ^ (row & 7)) << 4));
            }
#pragma unroll
            for (int mi = 0; mi < 4; ++mi)
#pragma unroll
                for (int nj = 0; nj < 4; ++nj)
                    mma_f16(acc[mi][nj], af[mi], &bf[nj >> 1][(nj & 1) * 2]);
        }
        __syncthreads();
    }

    const int g = lane >> 2, tg = lane & 3;
#pragma unroll
    for (int mi = 0; mi < 4; ++mi) {
        const int r0 = m0 + wm * 64 + mi * 16 + g;
#pragma unroll
        for (int nj = 0; nj < 4; ++nj) {
            const int col = n0 + wn * 32 + nj * 8 + tg * 2;
            float b0 = 0.0f, b1 = 0.0f;
            if (bias) { b0 = bias[col]; b1 = bias[col + 1]; }
            float2 o0 = make_float2(acc[mi][nj][0] + b0, acc[mi][nj][1] + b1);
            float2 o1 = make_float2(acc[mi][nj][2] + b0, acc[mi][nj][3] + b1);
            *(float2*)&C[(size_t)r0 * Nglob + col]       = o0;
            *(float2*)&C[(size_t)(r0 + 8) * Nglob + col] = o1;
        }
    }
}

// =============================================================================
// FUSED kernel: knn_scan + QKV GEMM in one launch. The two chains are
// dataflow-independent; interleaving (scan = every 4th blockIdx) gives each
// SM wave a mix, so scan's ALU/LDS work overlaps GEMM's tensor/cp.async work.
// =============================================================================
__global__ void __launch_bounds__(256, 2) fused_scan_qkv_kernel(
    const float* __restrict__ pos,
    const __half* __restrict__ A, const __half* __restrict__ Bt,
    float* __restrict__ C)
{
    extern __shared__ char sm[];
    const int bid = blockIdx.x;
    if ((bid & 3) == 0) {
        const int s = bid >> 2;                    // [0, 512)
        knn_scan_body(s & 63, s >> 6, pos, sm);
    } else {
        const int g = bid - (bid >> 2) - 1;        // [0, 1536)
        gemm_body(g % (NQKV / 128), g / (NQKV / 128), sm,
                  A, Bt, C, nullptr, NQKV, K2_QKV);
    }
}

// Standalone GEMM kernel (out-projection)
__global__ void __launch_bounds__(256, 2) gemm_mma_kernel(
    const __half* __restrict__ A, const __half* __restrict__ Bt,
    float* __restrict__ C, const float* __restrict__ bias,
    int Nglob, int K2)
{
    extern __shared__ char smem[];
    gemm_body(blockIdx.x, blockIdx.y, smem, A, Bt, C, bias, Nglob, K2);
}

// =============================================================================
// KNN merge: per query, 8-way merge of sorted 8-lists with (dist, idx)
// tie-break (lower index wins) — exact jax.lax.top_k order.
// =============================================================================
__global__ void __launch_bounds__(256) knn_merge_kernel()
{
    const int q = blockIdx.x * 256 + threadIdx.x;
    const float* pd = g_PD + (size_t)q * (NSLICE * 8);
    const int*   pi = g_PI + (size_t)q * (NSLICE * 8);
    const float INF = __int_as_float(0x7f800000);

    float hd[NSLICE]; int hi_[NSLICE]; int pp[NSLICE];
#pragma unroll
    for (int s = 0; s < NSLICE; ++s) {
        hd[s] = pd[s * 8]; hi_[s] = pi[s * 8]; pp[s] = 0;
    }

    int out[8];
#pragma unroll
    for (int r = 0; r < 8; ++r) {
        float bdv = hd[0]; int biv = hi_[0]; int sel = 0;
#pragma unroll
        for (int s = 1; s < NSLICE; ++s)
            if (hd[s] < bdv || (hd[s] == bdv && hi_[s] < biv)) {
                bdv = hd[s]; biv = hi_[s]; sel = s;
            }
        out[r] = biv;
#pragma unroll
        for (int s = 0; s < NSLICE; ++s)
            if (sel == s) {
                ++pp[s];
                const bool ok = pp[s] < 8;
                hd[s]  = ok ? pd[s * 8 + pp[s]] : INF;
                hi_[s] = ok ? pi[s * 8 + pp[s]] : 0x7fffffff;
            }
    }
    *(int4*)&g_IDX[(size_t)q * 8]     = make_int4(out[0], out[1], out[2], out[3]);
    *(int4*)&g_IDX[(size_t)q * 8 + 4] = make_int4(out[4], out[5], out[6], out[7]);
}

// =============================================================================
// Conversions: fp32 -> fp16 (A: hi|lo split, B: hi duplicated), extended-K.
// =============================================================================
__global__ void __launch_bounds__(256) conv_x_kernel(const float* __restrict__ x)
{
    const int idx = blockIdx.x * 256 + threadIdx.x;
    const int row = idx >> 8, k = idx & 255;
    __half h, l;
    split_f16(x[idx], h, l);
    __half* r = g_X2 + (size_t)row * K2_QKV;
    r[k] = h; r[DD + k] = l;
}

__global__ void __launch_bounds__(256) conv_wqkv_kernel(const float* __restrict__ Wq,
                                                        const float* __restrict__ Wkv)
{
    const int idx = blockIdx.x * 256 + threadIdx.x;
    const int n = idx >> 8, k = idx & 255;
    const float v = (n < INNER) ? Wq[(size_t)k * INNER + n]
                                : Wkv[(size_t)k * (2 * INNER) + (n - INNER)];
    const __half h = __float2half(v);
    __half* r = g_WT + (size_t)n * K2_QKV;
    r[k] = h; r[DD + k] = h;
}

__global__ void __launch_bounds__(256) conv_wout_kernel(const float* __restrict__ Wout)
{
    const int idx = blockIdx.x * 256 + threadIdx.x;
    const int n = idx >> 9, k = idx & 511;
    const __half h = __float2half(Wout[(size_t)k * DD + n]);
    __half* r = g_WTO + (size_t)n * K2_OUT;
    r[k] = h; r[INNER + k] = h;
}

// =============================================================================
// Attention (unchanged): one block per point, 8 warps = 8 heads.
// =============================================================================
__global__ void __launch_bounds__(256) attn_kernel()
{
    const int point = blockIdx.x;
    const int warp  = threadIdx.x >> 5;
    const int lane  = threadIdx.x & 31;
    const int b     = point >> 13;
    const int baseb = b * NN;

    const int* idxp = g_IDX + (size_t)point * 8;
    const float2 qh = *(const float2*)&g_QKV[(size_t)point * NQKV + warp * DHD + lane * 2];

    float dots[8];
    int   nbs[8];
#pragma unroll
    for (int k = 0; k < 8; ++k) {
        const int nb = idxp[k];
        nbs[k] = nb;
        const float2 kk = *(const float2*)&g_QKV[(size_t)(baseb + nb) * NQKV + INNER + warp * DHD + lane * 2];
        float d = qh.x * kk.x + qh.y * kk.y;
#pragma unroll
        for (int o = 16; o; o >>= 1) d += __shfl_xor_sync(0xffffffffu, d, o);
        dots[k] = d * 0.125f;
    }

    float m = dots[0];
#pragma unroll
    for (int k = 1; k < 8; ++k) m = fmaxf(m, dots[k]);
    float e[8], s = 0.0f;
#pragma unroll
    for (int k = 0; k < 8; ++k) { e[k] = expf(dots[k] - m); s += e[k]; }
    const float inv = 1.0f / s;

    float2 acc = make_float2(0.0f, 0.0f);
#pragma unroll
    for (int k = 0; k < 8; ++k) {
        const float2 vv = *(const float2*)&g_QKV[(size_t)(baseb + nbs[k]) * NQKV + 2 * INNER + warp * DHD + lane * 2];
        const float a = e[k] * inv;
        acc.x = fmaf(a, vv.x, acc.x);
        acc.y = fmaf(a, vv.y, acc.y);
    }

    __half hx, lx, hy, ly;
    split_f16(acc.x, hx, lx);
    split_f16(acc.y, hy, ly);
    __half2 hp; hp.x = hx; hp.y = hy;
    __half2 lp; lp.x = lx; lp.y = ly;
    __half* r = g_AT2 + (size_t)point * K2_OUT + warp * DHD + lane * 2;
    *(__half2*)(r)         = hp;
    *(__half2*)(r + INNER) = lp;
}

// =============================================================================
extern "C" void kernel_launch(void* const* d_in, const int* in_sizes, int n_in,
                              void* d_out, int out_size)
{
    const float* x    = (const float*)d_in[0];
    const float* pos  = (const float*)d_in[1];
    const float* Wq   = (const float*)d_in[2];
    const float* Wkv  = (const float*)d_in[3];
    const float* Wout = (const float*)d_in[4];
    const float* bout = (const float*)d_in[5];
    float* out = (float*)d_out;

    cudaFuncSetAttribute(gemm_mma_kernel,
                         cudaFuncAttributeMaxDynamicSharedMemorySize, GEMM_SMEM);
    cudaFuncSetAttribute(fused_scan_qkv_kernel,
                         cudaFuncAttributeMaxDynamicSharedMemorySize, GEMM_SMEM);

    __half *pX2, *pWT, *pWTO, *pAT2;
    float *pQKV;
    cudaGetSymbolAddress((void**)&pX2,  g_X2);
    cudaGetSymbolAddress((void**)&pWT,  g_WT);
    cudaGetSymbolAddress((void**)&pWTO, g_WTO);
    cudaGetSymbolAddress((void**)&pQKV, g_QKV);
    cudaGetSymbolAddress((void**)&pAT2, g_AT2);

    // 1-3) conversions (QKV GEMM inputs)
    conv_x_kernel<<<MTOT * DD / 256, 256>>>(x);
    conv_wqkv_kernel<<<NQKV * DD / 256, 256>>>(Wq, Wkv);
    conv_wout_kernel<<<DD * INNER / 256, 256>>>(Wout);

    // 4) FUSED: knn_scan + QKV GEMM (independent chains overlap) — profiled
    fused_scan_qkv_kernel<<<FUSED_GRID, 256, GEMM_SMEM>>>(pos, pX2, pWT, pQKV);

    // 5) KNN merge (8-way sorted merge, tie-break on index)
    knn_merge_kernel<<<MTOT / 256, 256>>>();

    // 6) neighbor attention
    attn_kernel<<<MTOT, 256>>>();

    // 7) out = ATT @ Wout + bout
    gemm_mma_kernel<<<dim3(DD / 128, MTOT / 128), 256, GEMM_SMEM>>>(
        pAT2, pWTO, out, bout, DD, K2_OUT);
}

// round 15
// speedup vs baseline: 1.0338x; 1.0220x over previous
#include <cuda_runtime.h>
#include <cuda_fp16.h>
#include <math.h>
#include <stdint.h>

// Problem constants
#define BB    2
#define NN    8192
#define DD    256
#define HH    8
#define DHD   64
#define KNB   8
#define INNER 512
#define MTOT  (BB*NN)        // 16384
#define NQKV  (3*INNER)      // 1536 = Q | K | V

// 2-term fp16 split as extended-K plain GEMM
#define K2_QKV (2*DD)        // 512
#define K2_OUT (2*INNER)     // 1024

// KNN slicing
#define NSLICE 8
#define SLICE  (NN / NSLICE)   // 1024 candidates per slice
#define KCAP   16              // per-thread append buffer entries

#define SCAN_BLOCKS (MTOT / 256 * NSLICE)     // 512
#define QKV_BLOCKS  (NQKV / 128 * MTOT / 128) // 1536
#define FUSED_GRID  (SCAN_BLOCKS + QKV_BLOCKS) // 2048 (scan = every 4th bid)

// ---------------- static device scratch ----------------
__device__ __half g_X2 [(size_t)MTOT * K2_QKV];      // 16.8 MB
__device__ __half g_WT [(size_t)NQKV * K2_QKV];      // 1.5 MB (N-major)
__device__ __half g_WTO[(size_t)DD * K2_OUT];        // 0.5 MB (N-major)
__device__ float  g_Qf [(size_t)MTOT * INNER];       // 33.5 MB (Q fp32)
__device__ __half g_KVh[(size_t)MTOT * (2*INNER)];   // 33.5 MB (K|V fp16)
__device__ __half g_AT2[(size_t)MTOT * K2_OUT];      // 33.6 MB
__device__ int    g_IDX[(size_t)MTOT * KNB];
__device__ float  g_PD [(size_t)MTOT * NSLICE * KNB];
__device__ int    g_PI [(size_t)MTOT * NSLICE * KNB];

__device__ __forceinline__ uint32_t smem_u32(const void* p) {
    uint32_t a;
    asm("{ .reg .u64 t; cvta.to.shared.u64 t, %1; cvt.u32.u64 %0, t; }" : "=r"(a) : "l"(p));
    return a;
}
__device__ __forceinline__ void cp_async16(uint32_t s, const void* g) {
    asm volatile("cp.async.cg.shared.global [%0], [%1], 16;" :: "r"(s), "l"(g));
}
#define CP_COMMIT()  asm volatile("cp.async.commit_group;" ::: "memory")
#define CP_WAIT2()   asm volatile("cp.async.wait_group 2;" ::: "memory")

__device__ __forceinline__ void split_f16(float v, __half& h, __half& l) {
    h = __float2half(v);
    l = __float2half(v - __half2float(h));
}

// =============================================================================
// KNN scan BODY: lane-per-query, branchless buffered selection. Lazy threshold
// only over-appends; flush drains in append(=index) order with strict-< ->
// exact jax.lax.top_k tie semantics.
// =============================================================================
__device__ __forceinline__ void knn_scan_body(int sbx, int slice,
                                              const float* __restrict__ pos,
                                              char* sm)
{
    float4* s_c4  = (float4*)sm;                          // 16KB
    float*  s_raw = (float*)(sm + 16384);                 // 12KB
    float2* s_buf = (float2*)(sm + 16384 + 12288);        // 32KB: [entry][tid]

    const int tid = threadIdx.x;
    const int q   = sbx * 256 + tid;
    const int b   = q >> 13;
    const int qn  = q & (NN - 1);
    const float* posb = pos + (size_t)b * NN * 3;

    const float qx2 = -2.0f * posb[qn * 3 + 0];
    const float qy2 = -2.0f * posb[qn * 3 + 1];
    const float qz2 = -2.0f * posb[qn * 3 + 2];

    {
        const float4* src = (const float4*)(posb + (size_t)slice * SLICE * 3);
#pragma unroll
        for (int i = 0; i < 3; ++i)
            ((float4*)s_raw)[tid + 256 * i] = src[tid + 256 * i];
    }
    __syncthreads();
#pragma unroll
    for (int i = 0; i < 4; ++i) {
        const int c = tid + 256 * i;
        const float cx = s_raw[c * 3 + 0];
        const float cy = s_raw[c * 3 + 1];
        const float cz = s_raw[c * 3 + 2];
        s_c4[c] = make_float4(cx, cy, cz, cx * cx + cy * cy + cz * cz);
    }
    __syncthreads();

    const float INF = __int_as_float(0x7f800000);
    float bd[8]; int bi[8];
#pragma unroll
    for (int j = 0; j < 8; ++j) { bd[j] = INF; bi[j] = 0x7fffffff; }
    float thr = INF;
    const int cbase = slice * SLICE;
    const uint32_t sbuf_tid = smem_u32(s_buf) + tid * 8;
    uint32_t addr = sbuf_tid;

    auto flush = [&]() {
        int count = (int)((addr - sbuf_tid) >> 11);
        int mx = count;
#pragma unroll
        for (int o = 16; o; o >>= 1) mx = max(mx, __shfl_xor_sync(0xffffffffu, mx, o));
        for (int k = 0; k < mx; ++k) {
            const float2 e = s_buf[k * 256 + tid];
            if (k < count && e.x < bd[7]) {
                bd[7] = e.x; bi[7] = __float_as_int(e.y);
#pragma unroll
                for (int u = 7; u > 0; --u) {
                    if (bd[u] < bd[u - 1]) {
                        float tf = bd[u - 1]; bd[u - 1] = bd[u]; bd[u] = tf;
                        int   ti = bi[u - 1]; bi[u - 1] = bi[u]; bi[u] = ti;
                    }
                }
            }
        }
        thr = bd[7];
        addr = sbuf_tid;
    };

    for (int c0 = 0; c0 < SLICE; c0 += 8) {
        float t[8];
#pragma unroll
        for (int u = 0; u < 8; ++u) {
            const float4 p = s_c4[c0 + u];
            t[u] = fmaf(p.x, qx2, fmaf(p.y, qy2, fmaf(p.z, qz2, p.w)));
        }
#pragma unroll
        for (int u = 0; u < 8; ++u) {
            asm volatile(
                "{\n\t.reg .pred p;\n\t"
                "setp.lt.f32 p, %1, %2;\n\t"
                "@p st.shared.v2.f32 [%0], {%1, %3};\n\t"
                "@p add.u32 %0, %0, 2048;\n\t}"
                : "+r"(addr)
                : "f"(t[u]), "f"(thr),
                  "f"(__int_as_float(cbase + c0 + u))
                : "memory");
        }
        if (__ballot_sync(0xffffffffu,
                          addr - sbuf_tid >= (KCAP - 8) * 2048))
            flush();
    }
    flush();

    float* pd = g_PD + ((size_t)q * NSLICE + slice) * 8;
    int*   pi = g_PI + ((size_t)q * NSLICE + slice) * 8;
#pragma unroll
    for (int j = 0; j < 8; ++j) { pd[j] = bd[j]; pi[j] = bi[j]; }
}

// =============================================================================
// fp16 tensor-core GEMM BODY (mainloop unchanged); epilogue is a functor
// epi(r0, col, o0, o1) with o0/o1 = float2 for rows r0 / r0+8.
// =============================================================================
#define GSTAGES   3
#define GSTAGE_B  32768
#define GEMM_SMEM (GSTAGES * GSTAGE_B)        // 96 KB

__device__ __forceinline__ void mma_f16(float* d, const uint32_t* a, const uint32_t* b)
{
    asm volatile(
        "mma.sync.aligned.m16n8k16.row.col.f32.f16.f16.f32 "
        "{%0,%1,%2,%3}, {%4,%5,%6,%7}, {%8,%9}, {%0,%1,%2,%3};"
        : "+f"(d[0]), "+f"(d[1]), "+f"(d[2]), "+f"(d[3])
        : "r"(a[0]), "r"(a[1]), "r"(a[2]), "r"(a[3]), "r"(b[0]), "r"(b[1]));
}

__device__ __forceinline__ void ldsm_x4(uint32_t* r, uint32_t a)
{
    asm volatile("ldmatrix.sync.aligned.m8n8.x4.shared.b16 {%0,%1,%2,%3}, [%4];"
        : "=r"(r[0]), "=r"(r[1]), "=r"(r[2]), "=r"(r[3]) : "r"(a));
}

// Epilogue functors (no --extended-lambda available in harness nvcc flags)
struct EpiQKV {
    __device__ __forceinline__ void operator()(int r0, int col,
                                               float2 o0, float2 o1) const {
        if (col < INNER) {                     // Q: fp32
            *(float2*)&g_Qf[(size_t)r0 * INNER + col]       = o0;
            *(float2*)&g_Qf[(size_t)(r0 + 8) * INNER + col] = o1;
        } else {                               // K|V: fp16
            const int c = col - INNER;
            *(__half2*)&g_KVh[(size_t)r0 * (2 * INNER) + c] =
                __floats2half2_rn(o0.x, o0.y);
            *(__half2*)&g_KVh[(size_t)(r0 + 8) * (2 * INNER) + c] =
                __floats2half2_rn(o1.x, o1.y);
        }
    }
};

struct EpiOut {
    float* C;
    const float* bias;
    __device__ __forceinline__ void operator()(int r0, int col,
                                               float2 o0, float2 o1) const {
        const float b0 = bias[col], b1 = bias[col + 1];
        o0.x += b0; o0.y += b1; o1.x += b0; o1.y += b1;
        *(float2*)&C[(size_t)r0 * DD + col]       = o0;
        *(float2*)&C[(size_t)(r0 + 8) * DD + col] = o1;
    }
};

template <typename Epi>
__device__ __forceinline__ void gemm_body(
    int bx, int by, char* smem,
    const __half* __restrict__ A,
    const __half* __restrict__ Bt,
    int K2, Epi epi)
{
    const uint32_t sb = smem_u32(smem);
    const int tid  = threadIdx.x;
    const int warp = tid >> 5, lane = tid & 31;
    const int wm = warp & 1, wn = warp >> 1;
    const int m0 = by * 128, n0 = bx * 128;
    const int nch = K2 >> 6;

    float acc[4][4][4];
#pragma unroll
    for (int i = 0; i < 4; ++i)
#pragma unroll
        for (int j = 0; j < 4; ++j)
#pragma unroll
            for (int t = 0; t < 4; ++t) acc[i][j][t] = 0.0f;

    const int a_row = wm * 64 + (lane & 15);
    const int a_k   = (lane >> 4);
    const int b_row = wn * 32 + ((lane & 16) >> 1) + (lane & 7);
    const int b_k   = ((lane >> 3) & 1);

    auto load_stage = [&](int s, int kc) {
        const uint32_t st = sb + s * GSTAGE_B;
#pragma unroll
        for (int it = 0; it < 4; ++it) {
            const int idx = it * 256 + tid;
            const int row = idx >> 3, c = idx & 7;
            cp_async16(st + row * 128 + ((c ^ (row & 7)) << 4),
                       A + (size_t)(m0 + row) * K2 + kc * 64 + c * 8);
        }
#pragma unroll
        for (int it = 0; it < 4; ++it) {
            const int idx = it * 256 + tid;
            const int row = idx >> 3, c = idx & 7;
            cp_async16(st + 16384 + row * 128 + ((c ^ (row & 7)) << 4),
                       Bt + (size_t)(n0 + row) * K2 + kc * 64 + c * 8);
        }
    };

    load_stage(0, 0); CP_COMMIT();
    load_stage(1, 1); CP_COMMIT();

    for (int i = 0; i < nch; ++i) {
        if (i + 2 < nch) load_stage((i + 2) % GSTAGES, i + 2);
        CP_COMMIT();
        CP_WAIT2();
        __syncthreads();

        const uint32_t stA = sb + (i % GSTAGES) * GSTAGE_B;
        const uint32_t stB = stA + 16384;

#pragma unroll
        for (int ks = 0; ks < 4; ++ks) {
            uint32_t af[4][4], bf[2][4];
#pragma unroll
            for (int mi = 0; mi < 4; ++mi) {
                const int row = a_row + mi * 16;
                const int kc  = 2 * ks + a_k;
                ldsm_x4(af[mi], stA + row * 128 + ((kc ^ (row & 7)) << 4));
            }
#pragma unroll
            for (int h = 0; h < 2; ++h) {
                const int row = b_row + h * 16;
                const int kc  = 2 * ks + b_k;
                ldsm_x4(bf[h], stB + row * 128 + ((kc ^ (row & 7)) << 4));
            }
#pragma unroll
            for (int mi = 0; mi < 4; ++mi)
#pragma unroll
                for (int nj = 0; nj < 4; ++nj)
                    mma_f16(acc[mi][nj], af[mi], &bf[nj >> 1][(nj & 1) * 2]);
        }
        __syncthreads();
    }

    const int g = lane >> 2, tg = lane & 3;
#pragma unroll
    for (int mi = 0; mi < 4; ++mi) {
        const int r0 = m0 + wm * 64 + mi * 16 + g;
#pragma unroll
        for (int nj = 0; nj < 4; ++nj) {
            const int col = n0 + wn * 32 + nj * 8 + tg * 2;
            float2 o0 = make_float2(acc[mi][nj][0], acc[mi][nj][1]);
            float2 o1 = make_float2(acc[mi][nj][2], acc[mi][nj][3]);
            epi(r0, col, o0, o1);
        }
    }
}

// =============================================================================
// FUSED kernel: knn_scan + QKV GEMM. Epilogue routes Q cols (fp32) vs K/V
// cols (fp16) — the branch is block-uniform (n0 multiple of 128).
// =============================================================================
__global__ void __launch_bounds__(256, 2) fused_scan_qkv_kernel(
    const float* __restrict__ pos,
    const __half* __restrict__ A, const __half* __restrict__ Bt)
{
    extern __shared__ char sm[];
    const int bid = blockIdx.x;
    if ((bid & 3) == 0) {
        const int s = bid >> 2;                    // [0, 512)
        knn_scan_body(s & 63, s >> 6, pos, sm);
    } else {
        const int g = bid - (bid >> 2) - 1;        // [0, 1536)
        gemm_body(g % (NQKV / 128), g / (NQKV / 128), sm, A, Bt, K2_QKV,
                  EpiQKV{});
    }
}

// Out-projection GEMM (fp32 output + bias)
__global__ void __launch_bounds__(256, 2) gemm_out_kernel(
    const __half* __restrict__ A, const __half* __restrict__ Bt,
    float* __restrict__ C, const float* __restrict__ bias)
{
    extern __shared__ char smem[];
    gemm_body(blockIdx.x, blockIdx.y, smem, A, Bt, K2_OUT, EpiOut{C, bias});
}

// =============================================================================
// KNN merge: 8-way merge of sorted 8-lists, (dist, idx) tie-break.
// =============================================================================
__global__ void __launch_bounds__(256) knn_merge_kernel()
{
    const int q = blockIdx.x * 256 + threadIdx.x;
    const float* pd = g_PD + (size_t)q * (NSLICE * 8);
    const int*   pi = g_PI + (size_t)q * (NSLICE * 8);
    const float INF = __int_as_float(0x7f800000);

    float hd[NSLICE]; int hi_[NSLICE]; int pp[NSLICE];
#pragma unroll
    for (int s = 0; s < NSLICE; ++s) {
        hd[s] = pd[s * 8]; hi_[s] = pi[s * 8]; pp[s] = 0;
    }

    int out[8];
#pragma unroll
    for (int r = 0; r < 8; ++r) {
        float bdv = hd[0]; int biv = hi_[0]; int sel = 0;
#pragma unroll
        for (int s = 1; s < NSLICE; ++s)
            if (hd[s] < bdv || (hd[s] == bdv && hi_[s] < biv)) {
                bdv = hd[s]; biv = hi_[s]; sel = s;
            }
        out[r] = biv;
#pragma unroll
        for (int s = 0; s < NSLICE; ++s)
            if (sel == s) {
                ++pp[s];
                const bool ok = pp[s] < 8;
                hd[s]  = ok ? pd[s * 8 + pp[s]] : INF;
                hi_[s] = ok ? pi[s * 8 + pp[s]] : 0x7fffffff;
            }
    }
    *(int4*)&g_IDX[(size_t)q * 8]     = make_int4(out[0], out[1], out[2], out[3]);
    *(int4*)&g_IDX[(size_t)q * 8 + 4] = make_int4(out[4], out[5], out[6], out[7]);
}

// =============================================================================
// Conversions (unchanged).
// =============================================================================
__global__ void __launch_bounds__(256) conv_x_kernel(const float* __restrict__ x)
{
    const int idx = blockIdx.x * 256 + threadIdx.x;
    const int row = idx >> 8, k = idx & 255;
    __half h, l;
    split_f16(x[idx], h, l);
    __half* r = g_X2 + (size_t)row * K2_QKV;
    r[k] = h; r[DD + k] = l;
}

__global__ void __launch_bounds__(256) conv_wqkv_kernel(const float* __restrict__ Wq,
                                                        const float* __restrict__ Wkv)
{
    const int idx = blockIdx.x * 256 + threadIdx.x;
    const int n = idx >> 8, k = idx & 255;
    const float v = (n < INNER) ? Wq[(size_t)k * INNER + n]
                                : Wkv[(size_t)k * (2 * INNER) + (n - INNER)];
    const __half h = __float2half(v);
    __half* r = g_WT + (size_t)n * K2_QKV;
    r[k] = h; r[DD + k] = h;
}

__global__ void __launch_bounds__(256) conv_wout_kernel(const float* __restrict__ Wout)
{
    const int idx = blockIdx.x * 256 + threadIdx.x;
    const int n = idx >> 9, k = idx & 511;
    const __half h = __float2half(Wout[(size_t)k * DD + n]);
    __half* r = g_WTO + (size_t)n * K2_OUT;
    r[k] = h; r[INNER + k] = h;
}

// =============================================================================
// Attention: Q fp32 from g_Qf, K/V fp16 from g_KVh (half the gather bytes).
// =============================================================================
__global__ void __launch_bounds__(256) attn_kernel()
{
    const int point = blockIdx.x;
    const int warp  = threadIdx.x >> 5;
    const int lane  = threadIdx.x & 31;
    const int b     = point >> 13;
    const int baseb = b * NN;

    const int* idxp = g_IDX + (size_t)point * 8;
    const float2 qh = *(const float2*)&g_Qf[(size_t)point * INNER + warp * DHD + lane * 2];

    float dots[8];
    int   nbs[8];
#pragma unroll
    for (int k = 0; k < 8; ++k) {
        const int nb = idxp[k];
        nbs[k] = nb;
        const __half2 kk2 = *(const __half2*)&g_KVh[(size_t)(baseb + nb) * (2 * INNER) + warp * DHD + lane * 2];
        const float2 kk = __half22float2(kk2);
        float d = qh.x * kk.x + qh.y * kk.y;
#pragma unroll
        for (int o = 16; o; o >>= 1) d += __shfl_xor_sync(0xffffffffu, d, o);
        dots[k] = d * 0.125f;
    }

    float m = dots[0];
#pragma unroll
    for (int k = 1; k < 8; ++k) m = fmaxf(m, dots[k]);
    float e[8], s = 0.0f;
#pragma unroll
    for (int k = 0; k < 8; ++k) { e[k] = expf(dots[k] - m); s += e[k]; }
    const float inv = 1.0f / s;

    float2 acc = make_float2(0.0f, 0.0f);
#pragma unroll
    for (int k = 0; k < 8; ++k) {
        const __half2 vv2 = *(const __half2*)&g_KVh[(size_t)(baseb + nbs[k]) * (2 * INNER) + INNER + warp * DHD + lane * 2];
        const float2 vv = __half22float2(vv2);
        const float a = e[k] * inv;
        acc.x = fmaf(a, vv.x, acc.x);
        acc.y = fmaf(a, vv.y, acc.y);
    }

    __half hx, lx, hy, ly;
    split_f16(acc.x, hx, lx);
    split_f16(acc.y, hy, ly);
    __half2 hp; hp.x = hx; hp.y = hy;
    __half2 lp; lp.x = lx; lp.y = ly;
    __half* r = g_AT2 + (size_t)point * K2_OUT + warp * DHD + lane * 2;
    *(__half2*)(r)         = hp;
    *(__half2*)(r + INNER) = lp;
}

// =============================================================================
extern "C" void kernel_launch(void* const* d_in, const int* in_sizes, int n_in,
                              void* d_out, int out_size)
{
    const float* x    = (const float*)d_in[0];
    const float* pos  = (const float*)d_in[1];
    const float* Wq   = (const float*)d_in[2];
    const float* Wkv  = (const float*)d_in[3];
    const float* Wout = (const float*)d_in[4];
    const float* bout = (const float*)d_in[5];
    float* out = (float*)d_out;

    cudaFuncSetAttribute(gemm_out_kernel,
                         cudaFuncAttributeMaxDynamicSharedMemorySize, GEMM_SMEM);
    cudaFuncSetAttribute(fused_scan_qkv_kernel,
                         cudaFuncAttributeMaxDynamicSharedMemorySize, GEMM_SMEM);

    __half *pX2, *pWT, *pWTO, *pAT2;
    cudaGetSymbolAddress((void**)&pX2,  g_X2);
    cudaGetSymbolAddress((void**)&pWT,  g_WT);
    cudaGetSymbolAddress((void**)&pWTO, g_WTO);
    cudaGetSymbolAddress((void**)&pAT2, g_AT2);

    // 1-3) conversions (QKV GEMM inputs)
    conv_x_kernel<<<MTOT * DD / 256, 256>>>(x);
    conv_wqkv_kernel<<<NQKV * DD / 256, 256>>>(Wq, Wkv);
    conv_wout_kernel<<<DD * INNER / 256, 256>>>(Wout);

    // 4) FUSED: knn_scan + QKV GEMM (Q fp32, K/V fp16) — profiled slot
    fused_scan_qkv_kernel<<<FUSED_GRID, 256, GEMM_SMEM>>>(pos, pX2, pWT);

    // 5) KNN merge
    knn_merge_kernel<<<MTOT / 256, 256>>>();

    // 6) neighbor attention (fp16 K/V gather — half the bytes)
    attn_kernel<<<MTOT, 256>>>();

    // 7) out = ATT @ Wout + bout
    gemm_out_kernel<<<dim3(DD / 128, MTOT / 128), 256, GEMM_SMEM>>>(
        pAT2, pWTO, out, bout);
}